// round 2
// baseline (speedup 1.0000x reference)
#include <cuda_runtime.h>
#include <cstdint>

#define N_NODES 500000
#define N_EDGES 16000000
#define IN_DIM 17

// Scratch: {sum, count} accumulator per node, plus the two scalar projections.
__device__ float2 g_acc[N_NODES];
__device__ float  g_proj[N_NODES];   // x . w_l   (message value per source node)
__device__ float  g_base[N_NODES];   // b_l + x . w_r

// ---------------------------------------------------------------------------
// Kernel 1: per-node projection + accumulator zeroing.
// ---------------------------------------------------------------------------
__global__ void __launch_bounds__(256) node_prep(
    const float* __restrict__ x,
    const float* __restrict__ w_l,
    const float* __restrict__ b_l,
    const float* __restrict__ w_r)
{
    int n = blockIdx.x * blockDim.x + threadIdx.x;
    if (n >= N_NODES) return;
    const float* xr = x + (size_t)n * IN_DIM;
    float pl = 0.f, pr = 0.f;
#pragma unroll
    for (int i = 0; i < IN_DIM; i++) {
        float v = __ldg(xr + i);
        pl = fmaf(v, __ldg(w_l + i), pl);
        pr = fmaf(v, __ldg(w_r + i), pr);
    }
    g_proj[n] = pl;
    g_base[n] = pr + __ldg(b_l);
    g_acc[n]  = make_float2(0.f, 0.f);
}

// ---------------------------------------------------------------------------
// Kernel 2: edge scatter. Indices are INT32 (JAX silently downgrades int64
// without x64 mode). Dominant cost = 128 MB of index reads from HBM.
// int4 loads: 4 edges per thread. One red.global.add.v2.f32 per edge
// accumulates {msg, 1.0} into g_acc[dst] (2 MB proj + 4 MB acc stay in L2).
// ---------------------------------------------------------------------------
__global__ void __launch_bounds__(256) edge_scatter(const int* __restrict__ ei)
{
    const int4* __restrict__ srcv = (const int4*)ei;
    const int4* __restrict__ dstv = (const int4*)(ei + N_EDGES);
    int i = blockIdx.x * blockDim.x + threadIdx.x;
    if (i >= N_EDGES / 4) return;

    int4 s = __ldg(&srcv[i]);
    int4 d = __ldg(&dstv[i]);

    float m0 = __ldg(&g_proj[s.x]);
    float m1 = __ldg(&g_proj[s.y]);
    float m2 = __ldg(&g_proj[s.z]);
    float m3 = __ldg(&g_proj[s.w]);
    const float one = 1.0f;

    asm volatile("red.global.add.v2.f32 [%0], {%1, %2};"
                 :: "l"(&g_acc[d.x]), "f"(m0), "f"(one) : "memory");
    asm volatile("red.global.add.v2.f32 [%0], {%1, %2};"
                 :: "l"(&g_acc[d.y]), "f"(m1), "f"(one) : "memory");
    asm volatile("red.global.add.v2.f32 [%0], {%1, %2};"
                 :: "l"(&g_acc[d.z]), "f"(m2), "f"(one) : "memory");
    asm volatile("red.global.add.v2.f32 [%0], {%1, %2};"
                 :: "l"(&g_acc[d.w]), "f"(m3), "f"(one) : "memory");
}

// ---------------------------------------------------------------------------
// Kernel 3: finalize. mean -> +base -> elu -> out linear.
// ---------------------------------------------------------------------------
__global__ void __launch_bounds__(256) finalize(
    float* __restrict__ out,
    const float* __restrict__ w_o,
    const float* __restrict__ b_o)
{
    int n = blockIdx.x * blockDim.x + threadIdx.x;
    if (n >= N_NODES) return;
    float2 a = g_acc[n];
    float mean = a.x / fmaxf(a.y, 1.0f);
    float h = mean + g_base[n];
    h = (h > 0.f) ? h : expm1f(h);          // elu, alpha=1
    out[n] = fmaf(h, __ldg(w_o), __ldg(b_o));
}

extern "C" void kernel_launch(void* const* d_in, const int* in_sizes, int n_in,
                              void* d_out, int out_size)
{
    const float* x    = (const float*)d_in[0];
    const int*   ei   = (const int*)d_in[1];
    // d_in[2] = edge_weight: unused (faithful to reference / PyG SAGEConv)
    const float* w_l  = (const float*)d_in[3];
    const float* b_l  = (const float*)d_in[4];
    const float* w_r  = (const float*)d_in[5];
    const float* w_o  = (const float*)d_in[6];
    const float* b_o  = (const float*)d_in[7];
    float*       out  = (float*)d_out;

    (void)in_sizes; (void)n_in; (void)out_size;

    const int T = 256;
    node_prep<<<(N_NODES + T - 1) / T, T>>>(x, w_l, b_l, w_r);
    edge_scatter<<<(N_EDGES / 4 + T - 1) / T, T>>>(ei);
    finalize<<<(N_NODES + T - 1) / T, T>>>(out, w_o, b_o);
}